// round 1
// baseline (speedup 1.0000x reference)
#include <cuda_runtime.h>

#define BATCH   16
#define CDIM    512
#define HIDDEN  512
#define NHEADS  8
#define DHEAD   64
#define NPIX    4096
#define O3      1536
#define LDIM    128
#define GEPS    1e-5f

typedef unsigned long long ull;

// ---------------- scratch (device globals: allocation-free) ----------------
__device__ float g_qkv [(size_t)BATCH * O3 * NPIX];      // 402.7 MB
__device__ float g_attn[(size_t)BATCH * HIDDEN * NPIX];  // 134.2 MB
__device__ float g_out2[(size_t)BATCH * CDIM * NPIX];    // 134.2 MB
__device__ float g_ctx [BATCH * NHEADS * DHEAD * DHEAD]; // 2 MB
__device__ float g_lk  [BATCH * HIDDEN];
__device__ float g_lv  [BATCH * HIDDEN];
__device__ float g_kmax[BATCH * HIDDEN];
__device__ float g_kinv[BATCH * HIDDEN];
__device__ float g_bsum [BATCH];
__device__ float g_bsumsq[BATCH];

// ---------------- f32x2 packed-FMA helpers ----------------
__device__ __forceinline__ ull pack2(float lo, float hi) {
    ull r; asm("mov.b64 %0, {%1,%2};" : "=l"(r) : "f"(lo), "f"(hi)); return r;
}
__device__ __forceinline__ void unpack2(ull v, float& lo, float& hi) {
    asm("mov.b64 {%0,%1}, %2;" : "=f"(lo), "=f"(hi) : "l"(v));
}
__device__ __forceinline__ void fma2(ull& d, ull a, ull b) {
    asm("fma.rn.f32x2 %0, %1, %2, %0;" : "+l"(d) : "l"(a), "l"(b));
}

// ---------------- init: zero GN stat accumulators ----------------
__global__ void k_init() {
    int t = threadIdx.x;
    if (t < BATCH) { g_bsum[t] = 0.f; g_bsumsq[t] = 0.f; }
}

// ---------------- label token projections ----------------
__global__ void k_lkv(const float* __restrict__ label,
                      const float* __restrict__ w_lk, const float* __restrict__ b_lk,
                      const float* __restrict__ w_lv, const float* __restrict__ b_lv) {
    int i = blockIdx.x * blockDim.x + threadIdx.x;
    const int total = BATCH * HIDDEN;
    if (i >= 2 * total) return;
    int which = i / total, r = i % total;
    int b = r / HIDDEN, o = r % HIDDEN;
    const float* w    = which ? w_lv : w_lk;
    const float* bias = which ? b_lv : b_lk;
    const float* lab = label + b * LDIM;
    const float* wr  = w + o * LDIM;
    float s = bias[o];
    #pragma unroll 8
    for (int j = 0; j < LDIM; j++) s += lab[j] * wr[j];
    if (which) g_lv[r] = s; else g_lk[r] = s;
}

// ---------------- SGEMM: C[o,p] = sum_c A[o,c] * B[c,p], B/C batched -------
// 128x128 block tile, K-chunk 8, 256 threads, 8x8 per-thread, f32x2 FMAs.
template<bool BS>
__global__ __launch_bounds__(256)
void k_sgemm(const float* __restrict__ A, const float* __restrict__ Bg,
             float* __restrict__ C, int Kdim, size_t strideB, size_t strideC,
             const float* __restrict__ bias) {
    const float* Bp = Bg + (size_t)blockIdx.z * strideB;
    float* Cp = C + (size_t)blockIdx.z * strideC;
    int o0 = blockIdx.y * 128, p0 = blockIdx.x * 128;
    __shared__ float As[8][128];
    __shared__ float Bs[8][128];
    int t = threadIdx.x;
    int aRow = t >> 1,  aCol = (t & 1) << 2;
    int bRow = t >> 5,  bCol = (t & 31) << 2;
    int tRow = t >> 4,  tCol = t & 15;

    ull acc2[8][4];
    #pragma unroll
    for (int i = 0; i < 8; i++)
        #pragma unroll
        for (int j = 0; j < 4; j++) acc2[i][j] = 0ull;

    for (int k0 = 0; k0 < Kdim; k0 += 8) {
        float4 av = *(const float4*)(A  + (size_t)(o0 + aRow) * Kdim + k0 + aCol);
        float4 bv = *(const float4*)(Bp + (size_t)(k0 + bRow) * NPIX + p0 + bCol);
        As[aCol + 0][aRow] = av.x; As[aCol + 1][aRow] = av.y;
        As[aCol + 2][aRow] = av.z; As[aCol + 3][aRow] = av.w;
        *(float4*)(&Bs[bRow][bCol]) = bv;
        __syncthreads();
        #pragma unroll
        for (int kk = 0; kk < 8; kk++) {
            float4 a0 = *(const float4*)(&As[kk][tRow * 4]);
            float4 a1 = *(const float4*)(&As[kk][tRow * 4 + 64]);
            float4 b0 = *(const float4*)(&Bs[kk][tCol * 4]);
            float4 b1 = *(const float4*)(&Bs[kk][tCol * 4 + 64]);
            ull ra[8] = {pack2(a0.x,a0.x), pack2(a0.y,a0.y), pack2(a0.z,a0.z), pack2(a0.w,a0.w),
                         pack2(a1.x,a1.x), pack2(a1.y,a1.y), pack2(a1.z,a1.z), pack2(a1.w,a1.w)};
            ull rb[4] = {pack2(b0.x,b0.y), pack2(b0.z,b0.w),
                         pack2(b1.x,b1.y), pack2(b1.z,b1.w)};
            #pragma unroll
            for (int i = 0; i < 8; i++)
                #pragma unroll
                for (int j = 0; j < 4; j++)
                    fma2(acc2[i][j], ra[i], rb[j]);
        }
        __syncthreads();
    }

    float lsum = 0.f, lsq = 0.f;
    #pragma unroll
    for (int i = 0; i < 8; i++) {
        float acc[8];
        #pragma unroll
        for (int j = 0; j < 4; j++) unpack2(acc2[i][j], acc[j * 2], acc[j * 2 + 1]);
        int o = o0 + tRow * 4 + (i & 3) + ((i >> 2) << 6);
        float bval = BS ? bias[o] : 0.f;
        float4 v0 = make_float4(acc[0] + bval, acc[1] + bval, acc[2] + bval, acc[3] + bval);
        float4 v1 = make_float4(acc[4] + bval, acc[5] + bval, acc[6] + bval, acc[7] + bval);
        float* crow = Cp + (size_t)o * NPIX + p0;
        *(float4*)(crow + tCol * 4)      = v0;
        *(float4*)(crow + 64 + tCol * 4) = v1;
        if (BS) {
            lsum += v0.x + v0.y + v0.z + v0.w + v1.x + v1.y + v1.z + v1.w;
            lsq  += v0.x*v0.x + v0.y*v0.y + v0.z*v0.z + v0.w*v0.w
                  + v1.x*v1.x + v1.y*v1.y + v1.z*v1.z + v1.w*v1.w;
        }
    }
    if (BS) {
        __shared__ float rsum[256], rsq[256];
        rsum[t] = lsum; rsq[t] = lsq;
        __syncthreads();
        for (int s = 128; s; s >>= 1) {
            if (t < s) { rsum[t] += rsum[t + s]; rsq[t] += rsq[t + s]; }
            __syncthreads();
        }
        if (t == 0) {
            atomicAdd(&g_bsum[blockIdx.z],   rsum[0]);
            atomicAdd(&g_bsumsq[blockIdx.z], rsq[0]);
        }
    }
}

// ---------------- k softmax row stats (over seq n+1, incl. label token) ----
__global__ void k_kstats() {
    int r = blockIdx.x;                       // 0 .. BATCH*HIDDEN-1
    const float* krow = g_qkv + ((size_t)(r / HIDDEN) * O3 + HIDDEN + (r % HIDDEN)) * NPIX;
    int t = threadIdx.x;
    __shared__ float red[256];
    float lm = -1e30f;
    for (int j = t; j < NPIX; j += 256) lm = fmaxf(lm, krow[j]);
    red[t] = lm; __syncthreads();
    for (int s = 128; s; s >>= 1) { if (t < s) red[t] = fmaxf(red[t], red[t + s]); __syncthreads(); }
    float m = fmaxf(red[0], g_lk[r]);
    __syncthreads();
    float ls = 0.f;
    for (int j = t; j < NPIX; j += 256) ls += __expf(krow[j] - m);
    red[t] = ls; __syncthreads();
    for (int s = 128; s; s >>= 1) { if (t < s) red[t] += red[t + s]; __syncthreads(); }
    if (t == 0) {
        g_kmax[r] = m;
        g_kinv[r] = 1.f / (red[0] + __expf(g_lk[r] - m));
    }
}

// ---------------- context[d,e] = sum_n softk(k)[d,n] * v[e,n] + label -----
__global__ __launch_bounds__(256) void k_context() {
    int b = blockIdx.x / NHEADS, h = blockIdx.x % NHEADS;
    const float* kbase = g_qkv + ((size_t)b * O3 + HIDDEN     + h * DHEAD) * NPIX;
    const float* vbase = g_qkv + ((size_t)b * O3 + 2 * HIDDEN + h * DHEAD) * NPIX;
    const float* km = g_kmax + b * HIDDEN + h * DHEAD;
    const float* ki = g_kinv + b * HIDDEN + h * DHEAD;
    __shared__ float ks[64][68];
    __shared__ float vs[64][68];
    int t = threadIdx.x;
    int tRow = t >> 4, tCol = t & 15;
    float acc[4][4] = {};
    for (int n0 = 0; n0 < NPIX; n0 += 64) {
        #pragma unroll
        for (int r = 0; r < 4; r++) {
            int idx = t + r * 256;
            int d = idx >> 4, n4 = (idx & 15) << 2;
            float4 kv = *(const float4*)(kbase + (size_t)d * NPIX + n0 + n4);
            float m = km[d], inv = ki[d];
            ks[n4 + 0][d] = __expf(kv.x - m) * inv;
            ks[n4 + 1][d] = __expf(kv.y - m) * inv;
            ks[n4 + 2][d] = __expf(kv.z - m) * inv;
            ks[n4 + 3][d] = __expf(kv.w - m) * inv;
            float4 vv = *(const float4*)(vbase + (size_t)d * NPIX + n0 + n4);
            vs[n4 + 0][d] = vv.x; vs[n4 + 1][d] = vv.y;
            vs[n4 + 2][d] = vv.z; vs[n4 + 3][d] = vv.w;
        }
        __syncthreads();
        #pragma unroll 8
        for (int nn = 0; nn < 64; nn++) {
            float ka[4], vb[4];
            *(float4*)ka = *(const float4*)(&ks[nn][tRow * 4]);
            *(float4*)vb = *(const float4*)(&vs[nn][tCol * 4]);
            #pragma unroll
            for (int i = 0; i < 4; i++)
                #pragma unroll
                for (int j = 0; j < 4; j++) acc[i][j] += ka[i] * vb[j];
        }
        __syncthreads();
    }
    const float* lkp = g_lk + b * HIDDEN + h * DHEAD;
    const float* lvp = g_lv + b * HIDDEN + h * DHEAD;
    float* cbase = g_ctx + (size_t)(b * NHEADS + h) * DHEAD * DHEAD;
    #pragma unroll
    for (int i = 0; i < 4; i++) {
        int d = tRow * 4 + i;
        float sl = __expf(lkp[d] - km[d]) * ki[d];
        #pragma unroll
        for (int j = 0; j < 4; j++) {
            int e = tCol * 4 + j;
            cbase[d * DHEAD + e] = acc[i][j] + sl * lvp[e];
        }
    }
}

// ------- q softmax (over d) fused with out[e,p] = sum_d ctx[d,e]*softq[d,p]
__global__ __launch_bounds__(256) void k_qattn() {
    int b = blockIdx.z, h = blockIdx.y, p0 = blockIdx.x * 64;
    const float* qbase = g_qkv + ((size_t)b * O3 + h * DHEAD) * NPIX;
    const float* cbase = g_ctx + (size_t)(b * NHEADS + h) * DHEAD * DHEAD;
    __shared__ float sq[64][68];
    __shared__ float cs[64][64];
    __shared__ float colmax[64], colscl[64], redm[4][64], reds[4][64];
    int t = threadIdx.x;
    #pragma unroll
    for (int r = 0; r < 4; r++) {
        int idx = t + r * 256;
        int d = idx >> 4, p4 = (idx & 15) << 2;
        *(float4*)(&sq[d][p4]) = *(const float4*)(qbase + (size_t)d * NPIX + p0 + p4);
        *(float4*)(&cs[d][p4]) = *(const float4*)(cbase + d * DHEAD + p4);
    }
    __syncthreads();
    int p = t & 63, qg = t >> 6;
    float lm = -1e30f;
    for (int d = qg * 16; d < qg * 16 + 16; d++) lm = fmaxf(lm, sq[d][p]);
    redm[qg][p] = lm; __syncthreads();
    if (qg == 0)
        colmax[p] = fmaxf(fmaxf(redm[0][p], redm[1][p]), fmaxf(redm[2][p], redm[3][p]));
    __syncthreads();
    float cm = colmax[p], ls = 0.f;
    for (int d = qg * 16; d < qg * 16 + 16; d++) {
        float e = __expf(sq[d][p] - cm); sq[d][p] = e; ls += e;
    }
    reds[qg][p] = ls; __syncthreads();
    if (qg == 0)
        colscl[p] = 0.125f / (reds[0][p] + reds[1][p] + reds[2][p] + reds[3][p]);
    __syncthreads();
    float sc = colscl[p];
    for (int d = qg * 16; d < qg * 16 + 16; d++) sq[d][p] *= sc;
    __syncthreads();

    int tRow = t >> 4, tCol = t & 15;
    float acc[4][4] = {};
    #pragma unroll 8
    for (int d = 0; d < 64; d++) {
        float ce[4], qp[4];
        *(float4*)ce = *(const float4*)(&cs[d][tRow * 4]);
        *(float4*)qp = *(const float4*)(&sq[d][tCol * 4]);
        #pragma unroll
        for (int i = 0; i < 4; i++)
            #pragma unroll
            for (int j = 0; j < 4; j++) acc[i][j] += ce[i] * qp[j];
    }
    float* abase = g_attn + ((size_t)b * HIDDEN + h * DHEAD) * NPIX;
    #pragma unroll
    for (int i = 0; i < 4; i++) {
        int e = tRow * 4 + i;
        *(float4*)(abase + (size_t)e * NPIX + p0 + tCol * 4) =
            make_float4(acc[i][0], acc[i][1], acc[i][2], acc[i][3]);
    }
}

// ---------------- GroupNorm finalize ----------------
__global__ void k_finalize(const float* __restrict__ gn_g, const float* __restrict__ gn_b,
                           float* __restrict__ out) {
    size_t i = (size_t)blockIdx.x * blockDim.x + threadIdx.x;
    const size_t total4 = (size_t)BATCH * CDIM * NPIX / 4;
    if (i >= total4) return;
    size_t e = i * 4;
    int b = (int)(e / ((size_t)CDIM * NPIX));
    int c = (int)((e / NPIX) % CDIM);
    const float invM = 1.f / ((float)CDIM * NPIX);
    float mean = g_bsum[b] * invM;
    float var  = g_bsumsq[b] * invM - mean * mean;
    float inv  = rsqrtf(var + GEPS);
    float gg = gn_g[c] * inv;
    float bb = gn_b[c] - mean * gg;
    float4 v = *(const float4*)(g_out2 + e);
    *(float4*)(out + e) = make_float4(v.x * gg + bb, v.y * gg + bb,
                                      v.z * gg + bb, v.w * gg + bb);
}

// ---------------- launch ----------------
extern "C" void kernel_launch(void* const* d_in, const int* in_sizes, int n_in,
                              void* d_out, int out_size) {
    const float* x      = (const float*)d_in[0];
    const float* label  = (const float*)d_in[1];
    const float* w_qkv  = (const float*)d_in[2];
    const float* w_lk   = (const float*)d_in[3];
    const float* b_lk   = (const float*)d_in[4];
    const float* w_lv   = (const float*)d_in[5];
    const float* b_lv   = (const float*)d_in[6];
    const float* w_out  = (const float*)d_in[7];
    const float* b_out  = (const float*)d_in[8];
    const float* gn_g   = (const float*)d_in[9];
    const float* gn_b   = (const float*)d_in[10];
    float* out = (float*)d_out;

    float *qkv_p, *attn_p, *out2_p;
    cudaGetSymbolAddress((void**)&qkv_p,  g_qkv);
    cudaGetSymbolAddress((void**)&attn_p, g_attn);
    cudaGetSymbolAddress((void**)&out2_p, g_out2);

    k_init<<<1, 32>>>();
    k_lkv<<<(2 * BATCH * HIDDEN + 255) / 256, 256>>>(label, w_lk, b_lk, w_lv, b_lv);
    k_sgemm<false><<<dim3(NPIX / 128, O3 / 128, BATCH), 256>>>(
        w_qkv, x, qkv_p, CDIM, (size_t)CDIM * NPIX, (size_t)O3 * NPIX, nullptr);
    k_kstats<<<BATCH * HIDDEN, 256>>>();
    k_context<<<BATCH * NHEADS, 256>>>();
    k_qattn<<<dim3(NPIX / 64, NHEADS, BATCH), 256>>>();
    k_sgemm<true><<<dim3(NPIX / 128, HIDDEN / 128, BATCH), 256>>>(
        w_out, attn_p, out2_p, HIDDEN, (size_t)HIDDEN * NPIX, (size_t)CDIM * NPIX, b_out);
    k_finalize<<<(BATCH * CDIM * NPIX / 4 + 255) / 256, 256>>>(gn_g, gn_b, out);
}

// round 3
// speedup vs baseline: 1.8284x; 1.8284x over previous
#include <cuda_runtime.h>
#include <cuda_bf16.h>
#include <cstdint>

#define BATCH   16
#define CDIM    512
#define HIDDEN  512
#define NHEADS  8
#define DHEAD   64
#define NPIX    4096
#define O3      1536
#define LDIM    128
#define GEPS    1e-5f

// ---------------- scratch (device globals: allocation-free) ----------------
__device__ float g_qkv [(size_t)BATCH * O3 * NPIX];      // 402.7 MB fp32
__device__ float g_out2[(size_t)BATCH * CDIM * NPIX];    // 134.2 MB
__device__ float g_ctx [BATCH * NHEADS * DHEAD * DHEAD];
__device__ float g_lk  [BATCH * HIDDEN];
__device__ float g_lv  [BATCH * HIDDEN];
__device__ float g_kmax[BATCH * HIDDEN];
__device__ float g_kinv[BATCH * HIDDEN];
__device__ float g_bsum [BATCH];
__device__ float g_bsumsq[BATCH];
// bf16 hi/lo split operands for tensor GEMMs
__device__ __nv_bfloat16 g_wq_hi[(size_t)O3 * CDIM];
__device__ __nv_bfloat16 g_wq_lo[(size_t)O3 * CDIM];
__device__ __nv_bfloat16 g_wo_hi[(size_t)CDIM * HIDDEN];
__device__ __nv_bfloat16 g_wo_lo[(size_t)CDIM * HIDDEN];
__device__ __nv_bfloat16 g_xt_hi[(size_t)BATCH * NPIX * CDIM];   // x^T [b][p][c]
__device__ __nv_bfloat16 g_xt_lo[(size_t)BATCH * NPIX * CDIM];
__device__ __nv_bfloat16 g_at_hi[(size_t)BATCH * NPIX * HIDDEN]; // attn^T [b][p][e]
__device__ __nv_bfloat16 g_at_lo[(size_t)BATCH * NPIX * HIDDEN];

// ---------------- helpers ----------------
__device__ __forceinline__ uint32_t smem_u32(const void* p) {
    uint32_t a;
    asm("{ .reg .u64 t; cvta.to.shared.u64 t, %1; cvt.u32.u64 %0, t; }" : "=r"(a) : "l"(p));
    return a;
}
__device__ __forceinline__ void cp16(uint32_t d, const void* s) {
    asm volatile("cp.async.cg.shared.global [%0], [%1], 16;" :: "r"(d), "l"(s));
}
#define CP_COMMIT() asm volatile("cp.async.commit_group;" ::: "memory")
#define CP_WAIT1()  asm volatile("cp.async.wait_group 1;" ::: "memory")

__device__ __forceinline__ void ldsm4(uint32_t* r, uint32_t a) {
    asm volatile("ldmatrix.sync.aligned.m8n8.x4.shared.b16 {%0,%1,%2,%3}, [%4];"
                 : "=r"(r[0]), "=r"(r[1]), "=r"(r[2]), "=r"(r[3]) : "r"(a));
}
__device__ __forceinline__ void mma16816(float* c, const uint32_t* a, const uint32_t* b) {
    asm volatile("mma.sync.aligned.m16n8k16.row.col.f32.bf16.bf16.f32 "
                 "{%0,%1,%2,%3}, {%4,%5,%6,%7}, {%8,%9}, {%0,%1,%2,%3};"
                 : "+f"(c[0]), "+f"(c[1]), "+f"(c[2]), "+f"(c[3])
                 : "r"(a[0]), "r"(a[1]), "r"(a[2]), "r"(a[3]), "r"(b[0]), "r"(b[1]));
}
__device__ __forceinline__ uint32_t pack_bf2(float lo, float hi) {
    uint32_t r; asm("cvt.rn.bf16x2.f32 %0, %1, %2;" : "=r"(r) : "f"(hi), "f"(lo)); return r;
}
__device__ __forceinline__ float bfround(float x) {
    return __bfloat162float(__float2bfloat16(x));
}

// ---------------- init: zero GN stat accumulators ----------------
__global__ void k_init() {
    int t = threadIdx.x;
    if (t < BATCH) { g_bsum[t] = 0.f; g_bsumsq[t] = 0.f; }
}

// ---------------- label token projections ----------------
__global__ void k_lkv(const float* __restrict__ label,
                      const float* __restrict__ w_lk, const float* __restrict__ b_lk,
                      const float* __restrict__ w_lv, const float* __restrict__ b_lv) {
    int i = blockIdx.x * blockDim.x + threadIdx.x;
    const int total = BATCH * HIDDEN;
    if (i >= 2 * total) return;
    int which = i / total, r = i % total;
    int b = r / HIDDEN, o = r % HIDDEN;
    const float* w    = which ? w_lv : w_lk;
    const float* bias = which ? b_lv : b_lk;
    const float* lab = label + b * LDIM;
    const float* wr  = w + o * LDIM;
    float s = bias[o];
    #pragma unroll 8
    for (int j = 0; j < LDIM; j++) s += lab[j] * wr[j];
    if (which) g_lv[r] = s; else g_lk[r] = s;
}

// ---------------- hi/lo bf16 split (weights) ----------------
__global__ void k_split(const float* __restrict__ src, __nv_bfloat16* __restrict__ hi,
                        __nv_bfloat16* __restrict__ lo, int n4) {
    int i = blockIdx.x * blockDim.x + threadIdx.x;
    if (i >= n4) return;
    float4 v = ((const float4*)src)[i];
    uint2 h = make_uint2(pack_bf2(v.x, v.y), pack_bf2(v.z, v.w));
    uint2 l = make_uint2(pack_bf2(v.x - bfround(v.x), v.y - bfround(v.y)),
                         pack_bf2(v.z - bfround(v.z), v.w - bfround(v.w)));
    ((uint2*)hi)[i] = h;
    ((uint2*)lo)[i] = l;
}

// ------- transpose x [b,c,p] -> x^T [b,p,c] with hi/lo bf16 split ---------
__global__ __launch_bounds__(256) void k_txsplit(const float* __restrict__ x) {
    __shared__ float ts[32][129];
    int b = blockIdx.z, c0 = blockIdx.y * 32, p0 = blockIdx.x * 128;
    int t = threadIdx.x;
    const float* src = x + ((size_t)b * CDIM + c0) * NPIX + p0;
    #pragma unroll
    for (int r = 0; r < 4; r++) {
        int row = r * 8 + (t >> 5);
        float4 v = *(const float4*)(src + (size_t)row * NPIX + (t & 31) * 4);
        int c = (t & 31) * 4;
        ts[row][c] = v.x; ts[row][c + 1] = v.y; ts[row][c + 2] = v.z; ts[row][c + 3] = v.w;
    }
    __syncthreads();
    int pl = t >> 1, cb = (t & 1) * 16;
    float v[16];
    #pragma unroll
    for (int k = 0; k < 16; k++) v[k] = ts[cb + k][pl];
    uint32_t hw[8], lw[8];
    #pragma unroll
    for (int k = 0; k < 16; k += 2) {
        hw[k / 2] = pack_bf2(v[k], v[k + 1]);
        lw[k / 2] = pack_bf2(v[k] - bfround(v[k]), v[k + 1] - bfround(v[k + 1]));
    }
    size_t o = ((size_t)b * NPIX + p0 + pl) * CDIM + c0 + cb;
    uint4* dh = (uint4*)(g_xt_hi + o);
    uint4* dl = (uint4*)(g_xt_lo + o);
    dh[0] = make_uint4(hw[0], hw[1], hw[2], hw[3]);
    dh[1] = make_uint4(hw[4], hw[5], hw[6], hw[7]);
    dl[0] = make_uint4(lw[0], lw[1], lw[2], lw[3]);
    dl[1] = make_uint4(lw[4], lw[5], lw[6], lw[7]);
}

// ---------------- warp-MMA GEMM: C[o,p] = sum_c A[o,c]*B^T[p,c] ------------
// CTA tile 128x128, warps 4(M)x2(N), warp tile 32x64.
// K = 512 in 16 chunks of 32. 2-stage cp.async pipeline.
// smem per stage: 4 arrays (Ahi,Alo,Bhi,Blo), 128 rows x 80B.
#define ROWB     80
#define ARR_B    (128 * ROWB)         // 10240
#define STAGE_B  (4 * ARR_B)          // 40960
#define GSMEM    (2 * STAGE_B)        // 81920

template<bool BS>
__global__ __launch_bounds__(256, 2)
void k_mma(const __nv_bfloat16* __restrict__ Ahi, const __nv_bfloat16* __restrict__ Alo,
           const __nv_bfloat16* __restrict__ Bhi, const __nv_bfloat16* __restrict__ Blo,
           float* __restrict__ C, const float* __restrict__ bias,
           size_t strideB, size_t strideC) {
    extern __shared__ char smem[];
    uint32_t sb = smem_u32(smem);
    int t = threadIdx.x, w = t >> 5, lane = t & 31;
    int p0 = blockIdx.x * 128, o0 = blockIdx.y * 128, bz = blockIdx.z;
    const char* gp[4];
    gp[0] = (const char*)Ahi + (size_t)o0 * 1024;
    gp[1] = (const char*)Alo + (size_t)o0 * 1024;
    gp[2] = (const char*)(Bhi + (size_t)bz * strideB) + (size_t)p0 * 1024;
    gp[3] = (const char*)(Blo + (size_t)bz * strideB) + (size_t)p0 * 1024;
    float* Cp = C + (size_t)bz * strideC;

    int m0w = (w & 3) * 32, n0w = (w >> 2) * 64;

    float acc[2][8][4];
    #pragma unroll
    for (int mi = 0; mi < 2; mi++)
        #pragma unroll
        for (int ni = 0; ni < 8; ni++)
            #pragma unroll
            for (int q = 0; q < 4; q++) acc[mi][ni][q] = 0.f;

    // issue copy for k-chunk i into stage s
    auto issue = [&](int i, int s) {
        uint32_t sbase = sb + s * STAGE_B;
        int koff = i * 64;  // 32 bf16 = 64 bytes
        #pragma unroll
        for (int j = 0; j < 8; j++) {
            int arr = j >> 1;
            int rem = t + ((j & 1) << 8);
            int row = rem >> 2, ch = rem & 3;
            cp16(sbase + arr * ARR_B + row * ROWB + ch * 16,
                 gp[arr] + (size_t)row * 1024 + koff + ch * 16);
        }
    };

    issue(0, 0); CP_COMMIT();
    issue(1, 1); CP_COMMIT();

    int arow = lane & 15, achk = lane >> 4;
    int brow = (lane & 7) + ((lane >> 4) & 1) * 8, bchk = (lane >> 3) & 1;

    for (int i = 0; i < 16; i++) {
        CP_WAIT1();
        __syncthreads();
        uint32_t sbase = sb + (i & 1) * STAGE_B;
        #pragma unroll
        for (int ks = 0; ks < 2; ks++) {
            uint32_t Ah[2][4], Al[2][4], Bf[8][2];
            #pragma unroll
            for (int mi = 0; mi < 2; mi++) {
                uint32_t ad = sbase + (m0w + mi * 16 + arow) * ROWB + ks * 32 + achk * 16;
                ldsm4(Ah[mi], ad);
                ldsm4(Al[mi], ad + ARR_B);
            }
            #pragma unroll
            for (int np = 0; np < 4; np++) {
                uint32_t bd = sbase + 2 * ARR_B + (n0w + np * 16 + brow) * ROWB + ks * 32 + bchk * 16;
                ldsm4(&Bf[2 * np][0], bd);
            }
            #pragma unroll
            for (int mi = 0; mi < 2; mi++)
                #pragma unroll
                for (int ni = 0; ni < 8; ni++) {
                    mma16816(acc[mi][ni], Ah[mi], Bf[ni]);
                    mma16816(acc[mi][ni], Al[mi], Bf[ni]);
                }
            #pragma unroll
            for (int np = 0; np < 4; np++) {
                uint32_t bd = sbase + 3 * ARR_B + (n0w + np * 16 + brow) * ROWB + ks * 32 + bchk * 16;
                ldsm4(&Bf[2 * np][0], bd);
            }
            #pragma unroll
            for (int mi = 0; mi < 2; mi++)
                #pragma unroll
                for (int ni = 0; ni < 8; ni++)
                    mma16816(acc[mi][ni], Ah[mi], Bf[ni]);
        }
        __syncthreads();
        if (i + 2 < 16) issue(i + 2, i & 1);
        CP_COMMIT();
    }

    // ---- epilogue: direct stores (full 32B sectors), optional bias + GN stats
    int g = lane >> 2, q = lane & 3;
    float lsum = 0.f, lsq = 0.f;
    #pragma unroll
    for (int mi = 0; mi < 2; mi++) {
        int row0 = o0 + m0w + mi * 16 + g;
        int row1 = row0 + 8;
        float b0 = BS ? bias[row0] : 0.f;
        float b1 = BS ? bias[row1] : 0.f;
        #pragma unroll
        for (int ni = 0; ni < 8; ni++) {
            int col = p0 + n0w + ni * 8 + q * 2;
            float c0 = acc[mi][ni][0] + b0, c1 = acc[mi][ni][1] + b0;
            float c2 = acc[mi][ni][2] + b1, c3 = acc[mi][ni][3] + b1;
            *(float2*)(Cp + (size_t)row0 * NPIX + col) = make_float2(c0, c1);
            *(float2*)(Cp + (size_t)row1 * NPIX + col) = make_float2(c2, c3);
            if (BS) {
                lsum += c0 + c1 + c2 + c3;
                lsq  += c0 * c0 + c1 * c1 + c2 * c2 + c3 * c3;
            }
        }
    }
    if (BS) {
        float* rs = (float*)smem;
        float* rq = rs + 256;
        __syncthreads();
        rs[t] = lsum; rq[t] = lsq;
        __syncthreads();
        for (int s = 128; s; s >>= 1) {
            if (t < s) { rs[t] += rs[t + s]; rq[t] += rq[t + s]; }
            __syncthreads();
        }
        if (t == 0) {
            atomicAdd(&g_bsum[bz],   rs[0]);
            atomicAdd(&g_bsumsq[bz], rq[0]);
        }
    }
}

// ---------------- k softmax row stats (over seq n+1, incl. label token) ----
__global__ void k_kstats() {
    int r = blockIdx.x;
    const float* krow = g_qkv + ((size_t)(r / HIDDEN) * O3 + HIDDEN + (r % HIDDEN)) * NPIX;
    int t = threadIdx.x;
    __shared__ float red[256];
    float lm = -1e30f;
    for (int j = t; j < NPIX; j += 256) lm = fmaxf(lm, krow[j]);
    red[t] = lm; __syncthreads();
    for (int s = 128; s; s >>= 1) { if (t < s) red[t] = fmaxf(red[t], red[t + s]); __syncthreads(); }
    float m = fmaxf(red[0], g_lk[r]);
    __syncthreads();
    float ls = 0.f;
    for (int j = t; j < NPIX; j += 256) ls += __expf(krow[j] - m);
    red[t] = ls; __syncthreads();
    for (int s = 128; s; s >>= 1) { if (t < s) red[t] += red[t + s]; __syncthreads(); }
    if (t == 0) {
        g_kmax[r] = m;
        g_kinv[r] = 1.f / (red[0] + __expf(g_lk[r] - m));
    }
}

// ---------------- context[d,e] = sum_n softk(k)[d,n] * v[e,n] + label -----
__global__ __launch_bounds__(256) void k_context() {
    int b = blockIdx.x / NHEADS, h = blockIdx.x % NHEADS;
    const float* kbase = g_qkv + ((size_t)b * O3 + HIDDEN     + h * DHEAD) * NPIX;
    const float* vbase = g_qkv + ((size_t)b * O3 + 2 * HIDDEN + h * DHEAD) * NPIX;
    const float* km = g_kmax + b * HIDDEN + h * DHEAD;
    const float* ki = g_kinv + b * HIDDEN + h * DHEAD;
    __shared__ float ks[64][68];
    __shared__ float vs[64][68];
    int t = threadIdx.x;
    int tRow = t >> 4, tCol = t & 15;
    float acc[4][4] = {};
    for (int n0 = 0; n0 < NPIX; n0 += 64) {
        #pragma unroll
        for (int r = 0; r < 4; r++) {
            int idx = t + r * 256;
            int d = idx >> 4, n4 = (idx & 15) << 2;
            float4 kv = *(const float4*)(kbase + (size_t)d * NPIX + n0 + n4);
            float m = km[d], inv = ki[d];
            ks[n4 + 0][d] = __expf(kv.x - m) * inv;
            ks[n4 + 1][d] = __expf(kv.y - m) * inv;
            ks[n4 + 2][d] = __expf(kv.z - m) * inv;
            ks[n4 + 3][d] = __expf(kv.w - m) * inv;
            float4 vv = *(const float4*)(vbase + (size_t)d * NPIX + n0 + n4);
            vs[n4 + 0][d] = vv.x; vs[n4 + 1][d] = vv.y;
            vs[n4 + 2][d] = vv.z; vs[n4 + 3][d] = vv.w;
        }
        __syncthreads();
        #pragma unroll 8
        for (int nn = 0; nn < 64; nn++) {
            float ka[4], vb[4];
            *(float4*)ka = *(const float4*)(&ks[nn][tRow * 4]);
            *(float4*)vb = *(const float4*)(&vs[nn][tCol * 4]);
            #pragma unroll
            for (int i = 0; i < 4; i++)
                #pragma unroll
                for (int j = 0; j < 4; j++) acc[i][j] += ka[i] * vb[j];
        }
        __syncthreads();
    }
    const float* lkp = g_lk + b * HIDDEN + h * DHEAD;
    const float* lvp = g_lv + b * HIDDEN + h * DHEAD;
    float* cbase = g_ctx + (size_t)(b * NHEADS + h) * DHEAD * DHEAD;
    #pragma unroll
    for (int i = 0; i < 4; i++) {
        int d = tRow * 4 + i;
        float sl = __expf(lkp[d] - km[d]) * ki[d];
        #pragma unroll
        for (int j = 0; j < 4; j++) {
            int e = tCol * 4 + j;
            cbase[d * DHEAD + e] = acc[i][j] + sl * lvp[e];
        }
    }
}

// ------- q softmax (over d) fused with out[e,p]; writes attn^T hi/lo bf16 --
__global__ __launch_bounds__(256) void k_qattn() {
    int b = blockIdx.z, h = blockIdx.y, p0 = blockIdx.x * 64;
    const float* qbase = g_qkv + ((size_t)b * O3 + h * DHEAD) * NPIX;
    const float* cbase = g_ctx + (size_t)(b * NHEADS + h) * DHEAD * DHEAD;
    __shared__ float sq[64][68];
    __shared__ float cs[64][64];
    __shared__ float colmax[64], colscl[64], redm[4][64], reds[4][64];
    int t = threadIdx.x;
    #pragma unroll
    for (int r = 0; r < 4; r++) {
        int idx = t + r * 256;
        int d = idx >> 4, p4 = (idx & 15) << 2;
        *(float4*)(&sq[d][p4]) = *(const float4*)(qbase + (size_t)d * NPIX + p0 + p4);
        *(float4*)(&cs[d][p4]) = *(const float4*)(cbase + d * DHEAD + p4);
    }
    __syncthreads();
    int p = t & 63, qg = t >> 6;
    float lm = -1e30f;
    for (int d = qg * 16; d < qg * 16 + 16; d++) lm = fmaxf(lm, sq[d][p]);
    redm[qg][p] = lm; __syncthreads();
    if (qg == 0)
        colmax[p] = fmaxf(fmaxf(redm[0][p], redm[1][p]), fmaxf(redm[2][p], redm[3][p]));
    __syncthreads();
    float cm = colmax[p], ls = 0.f;
    for (int d = qg * 16; d < qg * 16 + 16; d++) {
        float e = __expf(sq[d][p] - cm); sq[d][p] = e; ls += e;
    }
    reds[qg][p] = ls; __syncthreads();
    if (qg == 0)
        colscl[p] = 0.125f / (reds[0][p] + reds[1][p] + reds[2][p] + reds[3][p]);
    __syncthreads();
    float sc = colscl[p];
    for (int d = qg * 16; d < qg * 16 + 16; d++) sq[d][p] *= sc;
    __syncthreads();

    int tRow = t >> 4, tCol = t & 15;
    float acc[4][4] = {};
    #pragma unroll 8
    for (int d = 0; d < 64; d++) {
        float ce[4], qp[4];
        *(float4*)ce = *(const float4*)(&cs[d][tRow * 4]);
        *(float4*)qp = *(const float4*)(&sq[d][tCol * 4]);
        #pragma unroll
        for (int i = 0; i < 4; i++)
            #pragma unroll
            for (int j = 0; j < 4; j++) acc[i][j] += ce[i] * qp[j];
    }
    // write attn^T [b][p][e] hi/lo bf16; e = h*64 + tRow*4 + i, p = p0+tCol*4+j
    #pragma unroll
    for (int j = 0; j < 4; j++) {
        int pp = p0 + tCol * 4 + j;
        size_t o = ((size_t)b * NPIX + pp) * HIDDEN + h * DHEAD + tRow * 4;
        float v0 = acc[0][j], v1 = acc[1][j], v2 = acc[2][j], v3 = acc[3][j];
        uint2 hv = make_uint2(pack_bf2(v0, v1), pack_bf2(v2, v3));
        uint2 lv = make_uint2(pack_bf2(v0 - bfround(v0), v1 - bfround(v1)),
                              pack_bf2(v2 - bfround(v2), v3 - bfround(v3)));
        *(uint2*)(g_at_hi + o) = hv;
        *(uint2*)(g_at_lo + o) = lv;
    }
}

// ---------------- GroupNorm finalize ----------------
__global__ void k_finalize(const float* __restrict__ gn_g, const float* __restrict__ gn_b,
                           float* __restrict__ out) {
    size_t i = (size_t)blockIdx.x * blockDim.x + threadIdx.x;
    const size_t total4 = (size_t)BATCH * CDIM * NPIX / 4;
    if (i >= total4) return;
    size_t e = i * 4;
    int b = (int)(e / ((size_t)CDIM * NPIX));
    int c = (int)((e / NPIX) % CDIM);
    const float invM = 1.f / ((float)CDIM * NPIX);
    float mean = g_bsum[b] * invM;
    float var  = g_bsumsq[b] * invM - mean * mean;
    float inv  = rsqrtf(var + GEPS);
    float gg = gn_g[c] * inv;
    float bb = gn_b[c] - mean * gg;
    float4 v = *(const float4*)(g_out2 + e);
    *(float4*)(out + e) = make_float4(v.x * gg + bb, v.y * gg + bb,
                                      v.z * gg + bb, v.w * gg + bb);
}

// ---------------- launch ----------------
extern "C" void kernel_launch(void* const* d_in, const int* in_sizes, int n_in,
                              void* d_out, int out_size) {
    const float* x      = (const float*)d_in[0];
    const float* label  = (const float*)d_in[1];
    const float* w_qkv  = (const float*)d_in[2];
    const float* w_lk   = (const float*)d_in[3];
    const float* b_lk   = (const float*)d_in[4];
    const float* w_lv   = (const float*)d_in[5];
    const float* b_lv   = (const float*)d_in[6];
    const float* w_out  = (const float*)d_in[7];
    const float* b_out  = (const float*)d_in[8];
    const float* gn_g   = (const float*)d_in[9];
    const float* gn_b   = (const float*)d_in[10];
    float* out = (float*)d_out;

    float *qkv_p, *out2_p;
    __nv_bfloat16 *wqh, *wql, *woh, *wol, *xth, *xtl, *ath, *atl;
    cudaGetSymbolAddress((void**)&qkv_p,  g_qkv);
    cudaGetSymbolAddress((void**)&out2_p, g_out2);
    cudaGetSymbolAddress((void**)&wqh, g_wq_hi);
    cudaGetSymbolAddress((void**)&wql, g_wq_lo);
    cudaGetSymbolAddress((void**)&woh, g_wo_hi);
    cudaGetSymbolAddress((void**)&wol, g_wo_lo);
    cudaGetSymbolAddress((void**)&xth, g_xt_hi);
    cudaGetSymbolAddress((void**)&xtl, g_xt_lo);
    cudaGetSymbolAddress((void**)&ath, g_at_hi);
    cudaGetSymbolAddress((void**)&atl, g_at_lo);

    cudaFuncSetAttribute(k_mma<false>, cudaFuncAttributeMaxDynamicSharedMemorySize, GSMEM);
    cudaFuncSetAttribute(k_mma<true>,  cudaFuncAttributeMaxDynamicSharedMemorySize, GSMEM);

    k_init<<<1, 32>>>();
    k_lkv<<<(2 * BATCH * HIDDEN + 255) / 256, 256>>>(label, w_lk, b_lk, w_lv, b_lv);
    k_split<<<(O3 * CDIM / 4 + 255) / 256, 256>>>(w_qkv, wqh, wql, O3 * CDIM / 4);
    k_split<<<(CDIM * HIDDEN / 4 + 255) / 256, 256>>>(w_out, woh, wol, CDIM * HIDDEN / 4);
    k_txsplit<<<dim3(NPIX / 128, CDIM / 32, BATCH), 256>>>(x);
    k_mma<false><<<dim3(NPIX / 128, O3 / 128, BATCH), 256, GSMEM>>>(
        wqh, wql, xth, xtl, qkv_p, nullptr,
        (size_t)NPIX * CDIM, (size_t)O3 * NPIX);
    k_kstats<<<BATCH * HIDDEN, 256>>>();
    k_context<<<BATCH * NHEADS, 256>>>();
    k_qattn<<<dim3(NPIX / 64, NHEADS, BATCH), 256>>>();
    k_mma<true><<<dim3(NPIX / 128, CDIM / 128, BATCH), 256, GSMEM>>>(
        woh, wol, ath, atl, out2_p, b_out,
        (size_t)NPIX * HIDDEN, (size_t)CDIM * NPIX);
    k_finalize<<<(BATCH * CDIM * NPIX / 4 + 255) / 256, 256>>>(gn_g, gn_b, out);
}